// round 13
// baseline (speedup 1.0000x reference)
#include <cuda_runtime.h>
#include <cstdint>

#define NBINS 64
#define ROW_LEN 8192
#define WARPS_PER_BLOCK 4          // 4 warps, one HALF-row per CTA
#define BLOCK_THREADS (WARPS_PER_BLOCK * 32)
#define BLK_ELEMS (ROW_LEN / 2)                  // 4096 elements per CTA
#define WARP_ELEMS (BLK_ELEMS / WARPS_PER_BLOCK) // 1024 per warp
#define VECS (WARP_ELEMS / 4 / 32)               // 8 float4 per lane

// R12's half-row oversubscription (8192 CTAs, 16/SM, fine-grain CLC
// balancing) with the zero-kernel + global-atomic epilogue replaced by a
// size-2 CLUSTER: the two half-row CTAs of a row exchange their 64 integer
// partial counts over DSMEM and rank 0 writes the exact float result.
// Single kernel, no output pre-zeroing, bitwise-deterministic (integer sum).
// Counters: plain u32 slab [bin][lane]; word stride over lane = 1 ->
// bank = lane: every warp atomic is 1 wavefront; intra-warp same-word
// collisions impossible; cross-warp merges via atomicAdd. smem ~8.3 KB.
__global__ __launch_bounds__(BLOCK_THREADS, 16) __cluster_dims__(2, 1, 1)
void hist_rows_kernel(const float* __restrict__ x, float* __restrict__ out) {
    __shared__ unsigned int priv[NBINS][32];
    __shared__ unsigned int partial[NBINS];

    const int tid  = threadIdx.x;
    const int warp = tid >> 5;
    const int lane = tid & 31;
    const int row  = blockIdx.x >> 1;

    uint32_t rank;
    asm("mov.u32 %0, %%cluster_ctarank;" : "=r"(rank));

    unsigned int* cell = &priv[0][0] + lane;   // bank = lane forever

    // Zero counters (2048 words / 128 threads = 16 each).
    unsigned int* flat = &priv[0][0];
    #pragma unroll
    for (int i = 0; i < (NBINS * 32) / BLOCK_THREADS; i++)
        flat[tid + i * BLOCK_THREADS] = 0u;
    __syncthreads();

    const float4* __restrict__ xr =
        (const float4*)(x + (size_t)row * ROW_LEN + (size_t)rank * BLK_ELEMS
                        + (size_t)warp * WARP_ELEMS) + lane;

    const float scale = 64.0f / 6.0f;   // NBINS / (VMAX - VMIN), fp32-rounded like ref

    // Exactly the reference fp32 sequence per element: (x - VMIN), * scale,
    // floor (round toward -inf), clamp to [0, 63]; one conflict-free atomic.
    #define PROC4(v)                                                          \
        do {                                                                  \
            float _f[4] = {(v).x, (v).y, (v).z, (v).w};                       \
            _Pragma("unroll")                                                 \
            for (int _j = 0; _j < 4; _j++) {                                  \
                int _b = __float2int_rd(__fmul_rn(__fadd_rn(_f[_j], 3.0f), scale)); \
                _b = max(0, min(NBINS - 1, _b));                              \
                atomicAdd(&cell[_b * 32], 1u);                                \
            }                                                                 \
        } while (0)

    // 8 float4 per lane: batches of 4 in flight (evict-first streaming).
    #pragma unroll 1
    for (int it = 0; it < VECS; it += 4) {
        float4 v0 = __ldcs(&xr[(it + 0) * 32]);
        float4 v1 = __ldcs(&xr[(it + 1) * 32]);
        float4 v2 = __ldcs(&xr[(it + 2) * 32]);
        float4 v3 = __ldcs(&xr[(it + 3) * 32]);
        PROC4(v0);
        PROC4(v1);
        PROC4(v2);
        PROC4(v3);
    }
    #undef PROC4

    __syncthreads();

    // Local reduce into partial[bin] (threads 0..63; rotated column reads).
    if (tid < NBINS) {
        unsigned int s = 0;
        #pragma unroll
        for (int t = 0; t < 32; t++)
            s += priv[tid][(t + tid) & 31];
        partial[tid] = s;
    }

    // Cluster barrier: both CTAs' partials visible cluster-wide.
    asm volatile("barrier.cluster.arrive.aligned;" ::: "memory");
    asm volatile("barrier.cluster.wait.aligned;" ::: "memory");

    // Rank 0 combines via DSMEM and writes exact integer totals as floats.
    if (rank == 0 && tid < NBINS) {
        uint32_t laddr = (uint32_t)__cvta_generic_to_shared(&partial[tid]);
        uint32_t raddr, peer;
        asm("mapa.shared::cluster.u32 %0, %1, %2;"
            : "=r"(raddr) : "r"(laddr), "r"(1u));
        asm("ld.shared::cluster.u32 %0, [%1];" : "=r"(peer) : "r"(raddr));
        unsigned int total = partial[tid] + peer;
        out[(size_t)row * NBINS + tid] = (float)total * (1.0f / (float)ROW_LEN);
    }

    // Keep rank 1's smem alive until rank 0 has read it.
    asm volatile("barrier.cluster.arrive.aligned;" ::: "memory");
    asm volatile("barrier.cluster.wait.aligned;" ::: "memory");
}

extern "C" void kernel_launch(void* const* d_in, const int* in_sizes, int n_in,
                              void* d_out, int out_size) {
    const float* x = (const float*)d_in[0];
    float* out = (float*)d_out;

    int nrows = in_sizes[0] / ROW_LEN;             // 4096
    hist_rows_kernel<<<nrows * 2, BLOCK_THREADS>>>(x, out);  // 4096 clusters
}

// round 14
// speedup vs baseline: 1.2264x; 1.2264x over previous
#include <cuda_runtime.h>

#define NBINS 64
#define ROW_LEN 8192
#define WARPS_PER_BLOCK 4          // 4 warps, one HALF-row per block
#define BLOCK_THREADS (WARPS_PER_BLOCK * 32)
#define BLK_ELEMS (ROW_LEN / 2)                  // 4096 elements per block
#define WARP_ELEMS (BLK_ELEMS / WARPS_PER_BLOCK) // 1024 per warp
#define VECS (WARP_ELEMS / 4 / 32)               // 8 float4 per lane

// R12 (best: half-row oversubscription, 8192 blocks ~7 streamed waves,
// plain u32 [bin][lane] counters with bank = lane -> every warp atomic is
// one conflict-free wavefront) + two LSU trims:
//   - smem zeroing via contiguous uint4 (4x STS.128 vs 16x STS.32/thread)
//   - all 8 float4 loads per lane issued up front (deeper MLP at the seams)
// Output epilogue unchanged from R12: zero-kernel + fp32 atomicAdd of exact
// dyadic partials (n*2^-13, n<=8192 exactly representable -> the two-block
// sum is order-independent, i.e. deterministic).
__global__ void zero_out_kernel(float* __restrict__ out, int n) {
    int i = blockIdx.x * blockDim.x + threadIdx.x;
    if (i < n) out[i] = 0.0f;
}

__global__ __launch_bounds__(BLOCK_THREADS, 16)
void hist_rows_kernel(const float* __restrict__ x, float* __restrict__ out) {
    __shared__ unsigned int priv[NBINS][32];

    const int tid     = threadIdx.x;
    const int warp    = tid >> 5;
    const int lane    = tid & 31;
    const int row     = blockIdx.x >> 1;
    const int halfsel = blockIdx.x & 1;

    unsigned int* cell = &priv[0][0] + lane;   // bank = lane forever

    // Zero counters with vector stores: 2048 words = 512 uint4; 4 per thread,
    // contiguous per thread -> STS.128.
    {
        uint4* z = (uint4*)&priv[0][0];
        const uint4 zero4 = {0u, 0u, 0u, 0u};
        #pragma unroll
        for (int i = 0; i < 4; i++)
            z[tid * 4 + i] = zero4;
    }
    __syncthreads();

    const float4* __restrict__ xr =
        (const float4*)(x + (size_t)row * ROW_LEN + (size_t)halfsel * BLK_ELEMS
                        + (size_t)warp * WARP_ELEMS) + lane;

    const float scale = 64.0f / 6.0f;   // NBINS / (VMAX - VMIN), fp32-rounded like ref

    // Exactly the reference fp32 sequence per element: (x - VMIN), * scale,
    // floor (round toward -inf), clamp to [0, 63]; one conflict-free atomic.
    #define PROC4(v)                                                          \
        do {                                                                  \
            float _f[4] = {(v).x, (v).y, (v).z, (v).w};                       \
            _Pragma("unroll")                                                 \
            for (int _j = 0; _j < 4; _j++) {                                  \
                int _b = __float2int_rd(__fmul_rn(__fadd_rn(_f[_j], 3.0f), scale)); \
                _b = max(0, min(NBINS - 1, _b));                              \
                atomicAdd(&cell[_b * 32], 1u);                                \
            }                                                                 \
        } while (0)

    // All 8 float4 per lane issued before any consumption: maximal MLP,
    // evict-first streaming (data is touched exactly once).
    float4 v0 = __ldcs(&xr[0 * 32]);
    float4 v1 = __ldcs(&xr[1 * 32]);
    float4 v2 = __ldcs(&xr[2 * 32]);
    float4 v3 = __ldcs(&xr[3 * 32]);
    float4 v4 = __ldcs(&xr[4 * 32]);
    float4 v5 = __ldcs(&xr[5 * 32]);
    float4 v6 = __ldcs(&xr[6 * 32]);
    float4 v7 = __ldcs(&xr[7 * 32]);
    PROC4(v0);
    PROC4(v1);
    PROC4(v2);
    PROC4(v3);
    PROC4(v4);
    PROC4(v5);
    PROC4(v6);
    PROC4(v7);
    #undef PROC4

    __syncthreads();

    // Reduce + publish exact dyadic partial (order-independent fp32 sum).
    // Rotated column (t+bin)&31 keeps concurrent readers on distinct banks.
    if (tid < NBINS) {
        const int bin = tid;
        unsigned int s = 0;
        #pragma unroll
        for (int t = 0; t < 32; t++)
            s += priv[bin][(t + bin) & 31];
        atomicAdd(&out[(size_t)row * NBINS + bin],
                  (float)s * (1.0f / (float)ROW_LEN));
    }
}

extern "C" void kernel_launch(void* const* d_in, const int* in_sizes, int n_in,
                              void* d_out, int out_size) {
    const float* x = (const float*)d_in[0];
    float* out = (float*)d_out;

    int nrows = in_sizes[0] / ROW_LEN;             // 4096

    // out is poisoned by the harness: zero it first (graph-node cost ~0).
    zero_out_kernel<<<(nrows * NBINS + 255) / 256, 256>>>(out, nrows * NBINS);

    hist_rows_kernel<<<nrows * 2, BLOCK_THREADS>>>(x, out);  // half-row blocks
}

// round 15
// speedup vs baseline: 1.2279x; 1.0012x over previous
#include <cuda_runtime.h>

#define NBINS 64
#define ROW_LEN 8192
#define WARPS_PER_BLOCK 4          // 4 warps, one HALF-row per block
#define BLOCK_THREADS (WARPS_PER_BLOCK * 32)
#define BLK_ELEMS (ROW_LEN / 2)                  // 4096 elements per block
#define WARP_ELEMS (BLK_ELEMS / WARPS_PER_BLOCK) // 1024 per warp
#define VECS (WARP_ELEMS / 4 / 32)               // 8 float4 per lane

// R12 structure restored verbatim (the proven best across 14 variants):
// half-row oversubscription (8192 blocks, ~7 streamed waves, CLC balancing),
// plain u32 [bin][lane] counters (bank = lane -> every warp atomic is one
// conflict-free wavefront), batch-of-4 __ldcs loads (MLP sweet spot),
// zero-kernel + exact-dyadic fp32 atomic epilogue (order-independent since
// every partial and total is n*2^-13, n <= 8192: exactly representable).
// Micro-trims vs R12: lane-contiguous uint4 smem zeroing (4 issue slots vs
// 16, minimal crossbar phases) and a 128-thread split reduction.
__global__ void zero_out_kernel(float* __restrict__ out, int n) {
    int i = blockIdx.x * blockDim.x + threadIdx.x;
    if (i < n) out[i] = 0.0f;
}

__global__ __launch_bounds__(BLOCK_THREADS, 16)
void hist_rows_kernel(const float* __restrict__ x, float* __restrict__ out) {
    __shared__ unsigned int priv[NBINS][32];

    const int tid     = threadIdx.x;
    const int warp    = tid >> 5;
    const int lane    = tid & 31;
    const int row     = blockIdx.x >> 1;
    const int halfsel = blockIdx.x & 1;

    unsigned int* cell = &priv[0][0] + lane;   // bank = lane forever

    // Zero counters: 512 uint4, LANE-CONTIGUOUS (stride 16B between lanes ->
    // each STS.128 takes the minimum 4 crossbar phases, no conflicts).
    {
        uint4* z = (uint4*)&priv[0][0];
        const uint4 zero4 = {0u, 0u, 0u, 0u};
        #pragma unroll
        for (int i = 0; i < 4; i++)
            z[tid + i * BLOCK_THREADS] = zero4;
    }
    __syncthreads();

    const float4* __restrict__ xr =
        (const float4*)(x + (size_t)row * ROW_LEN + (size_t)halfsel * BLK_ELEMS
                        + (size_t)warp * WARP_ELEMS) + lane;

    const float scale = 64.0f / 6.0f;   // NBINS / (VMAX - VMIN), fp32-rounded like ref

    // Exactly the reference fp32 sequence per element: (x - VMIN), * scale,
    // floor (round toward -inf), clamp to [0, 63]; one conflict-free atomic.
    #define PROC4(v)                                                          \
        do {                                                                  \
            float _f[4] = {(v).x, (v).y, (v).z, (v).w};                       \
            _Pragma("unroll")                                                 \
            for (int _j = 0; _j < 4; _j++) {                                  \
                int _b = __float2int_rd(__fmul_rn(__fadd_rn(_f[_j], 3.0f), scale)); \
                _b = max(0, min(NBINS - 1, _b));                              \
                atomicAdd(&cell[_b * 32], 1u);                                \
            }                                                                 \
        } while (0)

    // 8 float4 per lane in batches of 4 (the measured MLP sweet spot),
    // evict-first streaming (data touched exactly once).
    #pragma unroll 1
    for (int it = 0; it < VECS; it += 4) {
        float4 v0 = __ldcs(&xr[(it + 0) * 32]);
        float4 v1 = __ldcs(&xr[(it + 1) * 32]);
        float4 v2 = __ldcs(&xr[(it + 2) * 32]);
        float4 v3 = __ldcs(&xr[(it + 3) * 32]);
        PROC4(v0);
        PROC4(v1);
        PROC4(v2);
        PROC4(v3);
    }
    #undef PROC4

    __syncthreads();

    // Split reduction: all 128 threads sum 16 columns of one bin-half
    // (bin = tid & 63, columns [16*(tid>>6), +16) with rotation), then the
    // two halves combine via shfl and threads < 64 publish.
    {
        const int bin  = tid & 63;
        const int hsel = tid >> 6;               // 0: cols 0..15, 1: 16..31
        unsigned int s = 0;
        #pragma unroll
        for (int t = 0; t < 16; t++)
            s += priv[bin][((hsel * 16) + ((t + bin) & 15)) ^ (hsel ? 0 : 0)];
        // simpler rotation within each half: columns hsel*16 + ((t+bin)&15)
        unsigned int other = __shfl_xor_sync(0xFFFFFFFFu, s, 0);  // placeholder no-op
        (void)other;
        // Combine across the two half-sums: thread pairs (tid, tid+64) hold
        // the halves of the same bin but sit in DIFFERENT warps, so use smem.
        __shared__ unsigned int hsum[2][NBINS];
        hsum[hsel][bin] = s;
        __syncthreads();
        if (tid < NBINS) {
            unsigned int total = hsum[0][tid] + hsum[1][tid];
            atomicAdd(&out[(size_t)row * NBINS + tid],
                      (float)total * (1.0f / (float)ROW_LEN));
        }
    }
}

extern "C" void kernel_launch(void* const* d_in, const int* in_sizes, int n_in,
                              void* d_out, int out_size) {
    const float* x = (const float*)d_in[0];
    float* out = (float*)d_out;

    int nrows = in_sizes[0] / ROW_LEN;             // 4096

    // out is poisoned by the harness: zero it first (graph-node cost ~0).
    zero_out_kernel<<<(nrows * NBINS + 255) / 256, 256>>>(out, nrows * NBINS);

    hist_rows_kernel<<<nrows * 2, BLOCK_THREADS>>>(x, out);  // half-row blocks
}

// round 16
// speedup vs baseline: 1.3282x; 1.0817x over previous
#include <cuda_runtime.h>

#define NBINS 64
#define ROW_LEN 8192
#define WARPS_PER_BLOCK 4          // 4 warps, one HALF-row per block
#define BLOCK_THREADS (WARPS_PER_BLOCK * 32)
#define BLK_ELEMS (ROW_LEN / 2)                  // 4096 elements per block
#define WARP_ELEMS (BLK_ELEMS / WARPS_PER_BLOCK) // 1024 per warp
#define VECS (WARP_ELEMS / 4 / 32)               // 8 float4 per lane

// R12 restored exactly (measured optimum across 15 variants):
//  - half-row oversubscription: 8192 blocks, ~7 streamed waves over 148 SMs
//    (16 resident/SM) so CLC work-stealing absorbs cross-CTA finish spread
//  - plain u32 [bin][lane] counters: word stride over lane = 1 -> bank =
//    lane, every warp-wide atomicAdd is exactly 1 conflict-free wavefront;
//    intra-warp same-word collisions impossible; cross-warp merged by atomic
//  - batch-of-4 __ldcs float4 loads (measured MLP sweet spot; deeper batches
//    regress via cross-CTA L1TEX-queue contention)
//  - zero-kernel + fp32 atomicAdd epilogue: every partial and total is an
//    exact dyadic n*2^-13 (n <= 8192), so the two-block sum is order-
//    independent -> deterministic
// Sole change vs R12: lane-contiguous uint4 smem zeroing (4 STS.128/thread
// instead of 16 STS.32/thread; stride 16B between lanes = minimal phases).
__global__ void zero_out_kernel(float* __restrict__ out, int n) {
    int i = blockIdx.x * blockDim.x + threadIdx.x;
    if (i < n) out[i] = 0.0f;
}

__global__ __launch_bounds__(BLOCK_THREADS, 16)
void hist_rows_kernel(const float* __restrict__ x, float* __restrict__ out) {
    __shared__ unsigned int priv[NBINS][32];

    const int tid     = threadIdx.x;
    const int warp    = tid >> 5;
    const int lane    = tid & 31;
    const int row     = blockIdx.x >> 1;
    const int halfsel = blockIdx.x & 1;

    unsigned int* cell = &priv[0][0] + lane;   // bank = lane forever

    // Zero counters: 2048 words = 512 uint4; lane-contiguous STS.128.
    {
        uint4* z = (uint4*)&priv[0][0];
        const uint4 zero4 = {0u, 0u, 0u, 0u};
        #pragma unroll
        for (int i = 0; i < 4; i++)
            z[tid + i * BLOCK_THREADS] = zero4;
    }
    __syncthreads();

    const float4* __restrict__ xr =
        (const float4*)(x + (size_t)row * ROW_LEN + (size_t)halfsel * BLK_ELEMS
                        + (size_t)warp * WARP_ELEMS) + lane;

    const float scale = 64.0f / 6.0f;   // NBINS / (VMAX - VMIN), fp32-rounded like ref

    // Exactly the reference fp32 sequence per element: (x - VMIN), * scale,
    // floor (round toward -inf), clamp to [0, 63]; one conflict-free atomic.
    #define PROC4(v)                                                          \
        do {                                                                  \
            float _f[4] = {(v).x, (v).y, (v).z, (v).w};                       \
            _Pragma("unroll")                                                 \
            for (int _j = 0; _j < 4; _j++) {                                  \
                int _b = __float2int_rd(__fmul_rn(__fadd_rn(_f[_j], 3.0f), scale)); \
                _b = max(0, min(NBINS - 1, _b));                              \
                atomicAdd(&cell[_b * 32], 1u);                                \
            }                                                                 \
        } while (0)

    // 8 float4 per lane in batches of 4 (measured sweet spot), evict-first
    // streaming (data touched exactly once).
    #pragma unroll 1
    for (int it = 0; it < VECS; it += 4) {
        float4 v0 = __ldcs(&xr[(it + 0) * 32]);
        float4 v1 = __ldcs(&xr[(it + 1) * 32]);
        float4 v2 = __ldcs(&xr[(it + 2) * 32]);
        float4 v3 = __ldcs(&xr[(it + 3) * 32]);
        PROC4(v0);
        PROC4(v1);
        PROC4(v2);
        PROC4(v3);
    }
    #undef PROC4

    __syncthreads();

    // Reduce + publish exact dyadic partial (order-independent fp32 sum).
    // Rotated column (t+bin)&31 keeps concurrent readers on distinct banks.
    if (tid < NBINS) {
        const int bin = tid;
        unsigned int s = 0;
        #pragma unroll
        for (int t = 0; t < 32; t++)
            s += priv[bin][(t + bin) & 31];
        atomicAdd(&out[(size_t)row * NBINS + bin],
                  (float)s * (1.0f / (float)ROW_LEN));
    }
}

extern "C" void kernel_launch(void* const* d_in, const int* in_sizes, int n_in,
                              void* d_out, int out_size) {
    const float* x = (const float*)d_in[0];
    float* out = (float*)d_out;

    int nrows = in_sizes[0] / ROW_LEN;             // 4096

    // out is poisoned by the harness: zero it first (graph-node cost ~0).
    zero_out_kernel<<<(nrows * NBINS + 255) / 256, 256>>>(out, nrows * NBINS);

    hist_rows_kernel<<<nrows * 2, BLOCK_THREADS>>>(x, out);  // half-row blocks
}